// round 7
// baseline (speedup 1.0000x reference)
#include <cuda_runtime.h>
#include <cuda_bf16.h>
#include <cstdint>

// ---------------- device scratch (no allocs allowed) ----------------
// W1 pre-swizzled images: [kt=4][hi 32KB | lo 32KB]  (B operand [N=256][K=64] per chunk)
__device__ __align__(16) unsigned char g_W1sw[4 * 65536];
// W2 pre-swizzled: [kt=2][hi 16KB | lo 16KB]  ([N=128][K=64] per chunk)
__device__ __align__(16) unsigned char g_W2sw[2 * 32768];

// ---------------- helpers ----------------
__device__ __forceinline__ uint32_t s2u(const void* p) {
    uint32_t a;
    asm("{ .reg .u64 t; cvta.to.shared.u64 t, %1; cvt.u32.u64 %0, t; }" : "=r"(a) : "l"(p));
    return a;
}
#define SW128(o) ((o) ^ (((o) >> 3) & 0x70))

#define LDSM4(R0, R1, R2, R3, A) \
    asm volatile("ldmatrix.sync.aligned.m8n8.x4.shared.b16 {%0,%1,%2,%3}, [%4];" \
                 : "=r"(R0), "=r"(R1), "=r"(R2), "=r"(R3) : "r"(A))

__device__ __forceinline__ void mma_bf16(float d[4], const uint32_t a[4], const uint32_t b[2]) {
    asm volatile(
        "mma.sync.aligned.m16n8k16.row.col.f32.bf16.bf16.f32 "
        "{%0,%1,%2,%3}, {%4,%5,%6,%7}, {%8,%9}, {%0,%1,%2,%3};"
        : "+f"(d[0]), "+f"(d[1]), "+f"(d[2]), "+f"(d[3])
        : "r"(a[0]), "r"(a[1]), "r"(a[2]), "r"(a[3]), "r"(b[0]), "r"(b[1]));
}

__device__ __forceinline__ void cpa16(uint32_t saddr, const void* g) {
    asm volatile("cp.async.cg.shared.global [%0], [%1], 16;" :: "r"(saddr), "l"(g));
}
#define CP_COMMIT() asm volatile("cp.async.commit_group;" ::: "memory")
#define CP_WAIT0()  asm volatile("cp.async.wait_group 0;" ::: "memory")

// h = relu( sigmoid(-uz) * tanh(uh) )   [GRU cell with h0 = 0]
__device__ __forceinline__ float gate_act(float uz, float uh) {
    float s = 1.0f / (1.0f + __expf(uz));
    float t = tanhf(uh);
    return fmaxf(s * t, 0.0f);
}

// ---------------- prep: combine W[0,0]+W[1,0], interleave z/h cols, split bf16, swizzle ----------------
__global__ void prep_kernel(const float* __restrict__ wz1, const float* __restrict__ wh1,
                            const float* __restrict__ wz2, const float* __restrict__ wh2) {
    int i = blockIdx.x * blockDim.x + threadIdx.x;   // 65536 threads
    {   // W1: B operand [n=256][k=256]; n=2j -> z_j, n=2j+1 -> h_j
        int nn = i >> 8, k = i & 255;
        int j = nn >> 1;
        const float* src = (nn & 1) ? wh1 : wz1;
        float w = src[k * 128 + j] + src[49152 + k * 128 + j];
        __nv_bfloat16 hb = __float2bfloat16(w);
        __nv_bfloat16 lb = __float2bfloat16(w - __bfloat162float(hb));
        int kt = k >> 6, kk = k & 63;
        uint32_t o = (uint32_t)(kt * 65536) + SW128((uint32_t)(nn * 128 + kk * 2));
        *(__nv_bfloat16*)(g_W1sw + o) = hb;
        *(__nv_bfloat16*)(g_W1sw + o + 32768) = lb;
    }
    if (i < 16384) {   // W2: [n=128][k=128]
        int nn = i >> 7, k = i & 127;
        int j = nn >> 1;
        const float* src = (nn & 1) ? wh2 : wz2;
        float w = src[k * 64 + j] + src[12288 + k * 64 + j];
        __nv_bfloat16 hb = __float2bfloat16(w);
        __nv_bfloat16 lb = __float2bfloat16(w - __bfloat162float(hb));
        int kt = k >> 6, kk = k & 63;
        uint32_t o = (uint32_t)(kt * 32768) + SW128((uint32_t)(nn * 128 + kk * 2));
        *(__nv_bfloat16*)(g_W2sw + o) = hb;
        *(__nv_bfloat16*)(g_W2sw + o + 16384) = lb;
    }
}

// =================== fused kernel: layer1 + layer2 + lin1 + lin2 ===================
// SMEM map:
//   [0      ] Abuf0 32K   (A chunk image: hi 16K | lo 16K)   -> later h1 image ck=0
//   [32768  ] Abuf1 32K                                       -> later h1 image ck=1
//   [65536  ] Bbuf0 64K   (B chunk: hi 32K | lo 32K)          -> later W2 image (2x32K)
//   [131072 ] Bbuf1 64K                                       -> later h2s (128*65*4)
//   [196608 ] w3s 4K
//   [200704 ] b3s(64) [200768] w4s(64) [200832] bz1(512) [201344] bh1(512)
//   [201856 ] bz2(256) [202112] bh2(256)   total 202368
#define SM_BYTES 202368

__global__ void __launch_bounds__(512, 1)
fused_mma(const float* __restrict__ x,
          const float* __restrict__ bz1, const float* __restrict__ bh1,
          const float* __restrict__ bz2, const float* __restrict__ bh2,
          const float* __restrict__ w3, const float* __restrict__ b3,
          const float* __restrict__ w4, const float* __restrict__ b4,
          float* __restrict__ out, int n) {
    extern __shared__ __align__(128) char sm[];
    const uint32_t sb = s2u(sm);
    const int tid = threadIdx.x, l = tid & 31, w = tid >> 5;
    const int wm = w >> 2, wn = w & 3;          // 4x4 warp grid

    float* w3s  = (float*)(sm + 196608);
    float* b3s  = (float*)(sm + 200704);
    float* w4s  = (float*)(sm + 200768);
    float* bz1s = (float*)(sm + 200832);
    float* bh1s = (float*)(sm + 201344);
    float* bz2s = (float*)(sm + 201856);
    float* bh2s = (float*)(sm + 202112);
    if (tid < 128) { bz1s[tid] = bz1[tid]; bh1s[tid] = bh1[tid]; }
    if (tid >= 128 && tid < 192) { bz2s[tid - 128] = bz2[tid - 128]; bh2s[tid - 128] = bh2[tid - 128]; }
    if (tid >= 192 && tid < 208) { b3s[tid - 192] = b3[tid - 192]; w4s[tid - 192] = w4[tid - 192]; }
    if (tid >= 256) w3s[tid - 256] = w3[tid - 256];
    if (tid >= 256) { w3s[tid] = w3[tid]; w3s[tid + 256] = w3[tid + 256]; w3s[tid + 512] = w3[tid + 512]; }

    // lane geometry for ldmatrix (phase 1: warp tile 32x64)
    const int arow0 = wm * 32 + (l & 15);
    const uint32_t kba = (uint32_t)(((l >> 4) & 1) * 16);
    const int brow0 = wn * 64 + 8 * ((l >> 4) & 1) + (l & 7);
    const uint32_t kbb = (uint32_t)(((l >> 3) & 1) * 16);

    const int r0 = blockIdx.x * 128;
    const int iq = tid & 15;

    float acc[2][8][4];
#pragma unroll
    for (int mi = 0; mi < 2; mi++)
#pragma unroll
        for (int nj = 0; nj < 8; nj++)
#pragma unroll
            for (int q = 0; q < 4; q++) acc[mi][nj][q] = 0.0f;

    float4 xr[4];
    // ---- prologue: x chunk0 into regs, B chunk0 via cp.async ----
#pragma unroll
    for (int p = 0; p < 4; p++) {
        int gr = r0 + (tid >> 4) + p * 32; if (gr >= n) gr = n - 1;
        xr[p] = *(const float4*)(x + (size_t)gr * 256 + iq * 4);
    }
    {
        const char* gB = (const char*)g_W1sw;
#pragma unroll
        for (int i = 0; i < 8; i++) {
            int idx = tid + i * 512;
            cpa16(sb + 65536u + (uint32_t)idx * 16u, gB + (size_t)idx * 16);
        }
        CP_COMMIT();
    }

    // =================== phase 1 mainloop: 4 K-chunks, double-buffered ===================
    for (int kt = 0; kt < 4; kt++) {
        const uint32_t aB = (uint32_t)(kt & 1) * 32768u;            // A buf base
        const uint32_t bB = 65536u + (uint32_t)(kt & 1) * 65536u;   // B buf base

        // convert prefetched regs -> A buf (swizzled bf16 hi/lo)
#pragma unroll
        for (int p = 0; p < 4; p++) {
            int row = (tid >> 4) + p * 32;
            float4 v = xr[p];
            __nv_bfloat16 h0 = __float2bfloat16(v.x), h1 = __float2bfloat16(v.y);
            __nv_bfloat16 h2 = __float2bfloat16(v.z), h3 = __float2bfloat16(v.w);
            __nv_bfloat16 l0 = __float2bfloat16(v.x - __bfloat162float(h0));
            __nv_bfloat16 l1 = __float2bfloat16(v.y - __bfloat162float(h1));
            __nv_bfloat16 l2 = __float2bfloat16(v.z - __bfloat162float(h2));
            __nv_bfloat16 l3 = __float2bfloat16(v.w - __bfloat162float(h3));
            uint32_t o = aB + SW128((uint32_t)(row * 128 + iq * 8));
            uint2 hp = make_uint2((uint32_t)__bfloat16_as_ushort(h0) | ((uint32_t)__bfloat16_as_ushort(h1) << 16),
                                  (uint32_t)__bfloat16_as_ushort(h2) | ((uint32_t)__bfloat16_as_ushort(h3) << 16));
            uint2 lp = make_uint2((uint32_t)__bfloat16_as_ushort(l0) | ((uint32_t)__bfloat16_as_ushort(l1) << 16),
                                  (uint32_t)__bfloat16_as_ushort(l2) | ((uint32_t)__bfloat16_as_ushort(l3) << 16));
            *(uint2*)(sm + o) = hp;
            *(uint2*)(sm + 16384 + o) = lp;
        }
        // prefetch next x chunk (LDG latency hidden behind this chunk's compute)
        if (kt < 3) {
#pragma unroll
            for (int p = 0; p < 4; p++) {
                int gr = r0 + (tid >> 4) + p * 32; if (gr >= n) gr = n - 1;
                xr[p] = *(const float4*)(x + (size_t)gr * 256 + (kt + 1) * 64 + iq * 4);
            }
        }
        CP_WAIT0();            // B chunk kt arrived
        __syncthreads();       // A stores visible; everyone done with retiring buffers

        // issue next B load (overlaps compute): kt<3 -> W1 chunk, kt==3 -> W2 (into Bbuf0)
        if (kt < 3) {
            const char* gB = (const char*)g_W1sw + (size_t)(kt + 1) * 65536;
            uint32_t dstB = 65536u + (uint32_t)((kt + 1) & 1) * 65536u;
#pragma unroll
            for (int i = 0; i < 8; i++) {
                int idx = tid + i * 512;
                cpa16(dstB + sb + (uint32_t)idx * 16u, gB + (size_t)idx * 16);
            }
            CP_COMMIT();
        } else {
            const char* gB = (const char*)g_W2sw;
#pragma unroll
            for (int i = 0; i < 8; i++) {
                int idx = tid + i * 512;
                cpa16(sb + 65536u + (uint32_t)idx * 16u, gB + (size_t)idx * 16);
            }
            CP_COMMIT();
        }

        // ---- compute: 3-term split (Ah·Bh, Al·Bh, Ah·Bl) ----
#pragma unroll
        for (int kk = 0; kk < 4; kk++) {
            uint32_t ah[2][4], al[2][4], bfr[8][2];
#pragma unroll
            for (int mi = 0; mi < 2; mi++) {
                int row = arow0 + mi * 16;
                uint32_t off = (uint32_t)(row * 128) + (((uint32_t)(kk * 32) + kba) ^ (uint32_t)((row & 7) << 4));
                LDSM4(ah[mi][0], ah[mi][1], ah[mi][2], ah[mi][3], sb + aB + off);
            }
#pragma unroll
            for (int g = 0; g < 4; g++) {
                int row = brow0 + g * 16;
                uint32_t off = (uint32_t)(row * 128) + (((uint32_t)(kk * 32) + kbb) ^ (uint32_t)((row & 7) << 4));
                LDSM4(bfr[2 * g][0], bfr[2 * g][1], bfr[2 * g + 1][0], bfr[2 * g + 1][1], sb + bB + off);
            }
#pragma unroll
            for (int mi = 0; mi < 2; mi++)
#pragma unroll
                for (int nj = 0; nj < 8; nj++) mma_bf16(acc[mi][nj], ah[mi], bfr[nj]);
#pragma unroll
            for (int mi = 0; mi < 2; mi++) {
                int row = arow0 + mi * 16;
                uint32_t off = (uint32_t)(row * 128) + (((uint32_t)(kk * 32) + kba) ^ (uint32_t)((row & 7) << 4));
                LDSM4(al[mi][0], al[mi][1], al[mi][2], al[mi][3], sb + aB + 16384u + off);
            }
#pragma unroll
            for (int mi = 0; mi < 2; mi++)
#pragma unroll
                for (int nj = 0; nj < 8; nj++) mma_bf16(acc[mi][nj], al[mi], bfr[nj]);
#pragma unroll
            for (int g = 0; g < 4; g++) {
                int row = brow0 + g * 16;
                uint32_t off = (uint32_t)(row * 128) + (((uint32_t)(kk * 32) + kbb) ^ (uint32_t)((row & 7) << 4));
                LDSM4(bfr[2 * g][0], bfr[2 * g][1], bfr[2 * g + 1][0], bfr[2 * g + 1][1], sb + bB + 32768u + off);
            }
#pragma unroll
            for (int mi = 0; mi < 2; mi++)
#pragma unroll
                for (int nj = 0; nj < 8; nj++) mma_bf16(acc[mi][nj], ah[mi], bfr[nj]);
        }
    }

    CP_WAIT0();            // W2 arrived
    __syncthreads();       // all phase-1 compute done

    // ---- phase-1 epilogue: act, bf16 split, h1 image -> Abuf0/Abuf1 ----
#pragma unroll
    for (int mi = 0; mi < 2; mi++)
#pragma unroll
        for (int nj = 0; nj < 8; nj++) {
            int rlo = wm * 32 + mi * 16 + (l >> 2);
            int j = wn * 32 + nj * 4 + (l & 3);
            float v0 = gate_act(acc[mi][nj][0] + bz1s[j], acc[mi][nj][1] + bh1s[j]);
            float v1 = gate_act(acc[mi][nj][2] + bz1s[j], acc[mi][nj][3] + bh1s[j]);
            int ck = j >> 6, kk2 = j & 63;
            uint32_t base = (uint32_t)ck * 32768u;
            {
                __nv_bfloat16 hb = __float2bfloat16(v0);
                __nv_bfloat16 lb = __float2bfloat16(v0 - __bfloat162float(hb));
                uint32_t o = base + SW128((uint32_t)(rlo * 128 + kk2 * 2));
                *(__nv_bfloat16*)(sm + o) = hb;
                *(__nv_bfloat16*)(sm + o + 16384) = lb;
            }
            {
                __nv_bfloat16 hb = __float2bfloat16(v1);
                __nv_bfloat16 lb = __float2bfloat16(v1 - __bfloat162float(hb));
                uint32_t o = base + SW128((uint32_t)((rlo + 8) * 128 + kk2 * 2));
                *(__nv_bfloat16*)(sm + o) = hb;
                *(__nv_bfloat16*)(sm + o + 16384) = lb;
            }
        }
    __syncthreads();

    // =================== phase 2: h2 = act(h1 @ W2), all in SMEM ===================
    // warp tile 32x32 (4x4 grid over 128x128)
    float acc2[2][4][4];
#pragma unroll
    for (int mi = 0; mi < 2; mi++)
#pragma unroll
        for (int nj = 0; nj < 4; nj++)
#pragma unroll
            for (int q = 0; q < 4; q++) acc2[mi][nj][q] = 0.0f;

    const int brow2 = wn * 32 + 8 * ((l >> 4) & 1) + (l & 7);

#pragma unroll
    for (int ck = 0; ck < 2; ck++) {
        const uint32_t aB = (uint32_t)ck * 32768u;
        const uint32_t bB = 65536u + (uint32_t)ck * 32768u;
#pragma unroll
        for (int kk = 0; kk < 4; kk++) {
            uint32_t ah[2][4], al[2][4], bfr[4][2];
#pragma unroll
            for (int mi = 0; mi < 2; mi++) {
                int row = arow0 + mi * 16;
                uint32_t off = (uint32_t)(row * 128) + (((uint32_t)(kk * 32) + kba) ^ (uint32_t)((row & 7) << 4));
                LDSM4(ah[mi][0], ah[mi][1], ah[mi][2], ah[mi][3], sb + aB + off);
            }
#pragma unroll
            for (int g = 0; g < 2; g++) {
                int row = brow2 + g * 16;
                uint32_t off = (uint32_t)(row * 128) + (((uint32_t)(kk * 32) + kbb) ^ (uint32_t)((row & 7) << 4));
                LDSM4(bfr[2 * g][0], bfr[2 * g][1], bfr[2 * g + 1][0], bfr[2 * g + 1][1], sb + bB + off);
            }
#pragma unroll
            for (int mi = 0; mi < 2; mi++)
#pragma unroll
                for (int nj = 0; nj < 4; nj++) mma_bf16(acc2[mi][nj], ah[mi], bfr[nj]);
#pragma unroll
            for (int mi = 0; mi < 2; mi++) {
                int row = arow0 + mi * 16;
                uint32_t off = (uint32_t)(row * 128) + (((uint32_t)(kk * 32) + kba) ^ (uint32_t)((row & 7) << 4));
                LDSM4(al[mi][0], al[mi][1], al[mi][2], al[mi][3], sb + aB + 16384u + off);
            }
#pragma unroll
            for (int mi = 0; mi < 2; mi++)
#pragma unroll
                for (int nj = 0; nj < 4; nj++) mma_bf16(acc2[mi][nj], al[mi], bfr[nj]);
#pragma unroll
            for (int g = 0; g < 2; g++) {
                int row = brow2 + g * 16;
                uint32_t off = (uint32_t)(row * 128) + (((uint32_t)(kk * 32) + kbb) ^ (uint32_t)((row & 7) << 4));
                LDSM4(bfr[2 * g][0], bfr[2 * g][1], bfr[2 * g + 1][0], bfr[2 * g + 1][1], sb + bB + 16384u + off);
            }
#pragma unroll
            for (int mi = 0; mi < 2; mi++)
#pragma unroll
                for (int nj = 0; nj < 4; nj++) mma_bf16(acc2[mi][nj], ah[mi], bfr[nj]);
        }
    }

    // ---- phase-2 epilogue: h2 -> smem (Bbuf1 region) ----
    float* h2s = (float*)(sm + 131072);   // [128][65]
#pragma unroll
    for (int mi = 0; mi < 2; mi++)
#pragma unroll
        for (int nj = 0; nj < 4; nj++) {
            int rlo = wm * 32 + mi * 16 + (l >> 2);
            int j = wn * 16 + nj * 4 + (l & 3);
            float v0 = gate_act(acc2[mi][nj][0] + bz2s[j], acc2[mi][nj][1] + bh2s[j]);
            float v1 = gate_act(acc2[mi][nj][2] + bz2s[j], acc2[mi][nj][3] + bh2s[j]);
            h2s[rlo * 65 + j] = v0;
            h2s[(rlo + 8) * 65 + j] = v1;
        }
    __syncthreads();

    // ---- lin1(relu) + lin2: one thread per row ----
    if (tid < 128) {
        float s[16];
#pragma unroll
        for (int u = 0; u < 16; u++) s[u] = b3s[u];
#pragma unroll 4
        for (int j = 0; j < 64; j++) {
            float v = h2s[tid * 65 + j];
#pragma unroll
            for (int u = 0; u < 16; u++) s[u] = fmaf(v, w3s[j * 16 + u], s[u]);
        }
        float o2 = __ldg(b4);
#pragma unroll
        for (int u = 0; u < 16; u++) o2 += fmaxf(s[u], 0.0f) * w4s[u];
        int gr = r0 + tid;
        if (gr < n) out[gr] = o2;
    }
}

extern "C" void kernel_launch(void* const* d_in, const int* in_sizes, int n_in,
                              void* d_out, int out_size) {
    const float* x   = (const float*)d_in[0];
    const float* wz1 = (const float*)d_in[3];
    const float* bz1 = (const float*)d_in[4];
    const float* wh1 = (const float*)d_in[7];
    const float* bh1 = (const float*)d_in[8];
    const float* wz2 = (const float*)d_in[9];
    const float* bz2 = (const float*)d_in[10];
    const float* wh2 = (const float*)d_in[13];
    const float* bh2 = (const float*)d_in[14];
    const float* w3  = (const float*)d_in[15];
    const float* b3  = (const float*)d_in[16];
    const float* w4  = (const float*)d_in[17];
    const float* b4  = (const float*)d_in[18];

    const int n  = in_sizes[0] / 256;          // 100000
    const int nb = (n + 127) / 128;            // 782

    cudaFuncSetAttribute(fused_mma, cudaFuncAttributeMaxDynamicSharedMemorySize, SM_BYTES);

    prep_kernel<<<256, 256>>>(wz1, wh1, wz2, wh2);
    fused_mma<<<nb, 512, SM_BYTES>>>(x, bz1, bh1, bz2, bh2, w3, b3, w4, b4,
                                     (float*)d_out, n);
}

// round 10
// speedup vs baseline: 1.3321x; 1.3321x over previous
#include <cuda_runtime.h>
#include <cuda_bf16.h>
#include <cstdint>

#define NB_MAX 782            // ceil(100000/128)

// ---------------- device scratch (no allocs allowed) ----------------
// W1 pre-swizzled images: [kt=4][hi 32KB | lo 32KB]  (B operand [N=256][K=64] per chunk)
__device__ __align__(16) unsigned char g_W1sw[4 * 65536];
// W2 pre-swizzled: [kt=2][hi 16KB | lo 16KB]  ([N=128][K=64] per chunk)
__device__ __align__(16) unsigned char g_W2sw[2 * 32768];
// h1 per-tile A images: [ck=2][hi 16KB | lo 16KB] = 64KB per 128-row tile
__device__ __align__(16) unsigned char g_h1img[(size_t)NB_MAX * 65536];

// ---------------- helpers ----------------
__device__ __forceinline__ uint32_t s2u(const void* p) {
    uint32_t a;
    asm("{ .reg .u64 t; cvta.to.shared.u64 t, %1; cvt.u32.u64 %0, t; }" : "=r"(a) : "l"(p));
    return a;
}
#define SW128(o) ((o) ^ (((o) >> 3) & 0x70))

#define LDSM4(R0, R1, R2, R3, A) \
    asm volatile("ldmatrix.sync.aligned.m8n8.x4.shared.b16 {%0,%1,%2,%3}, [%4];" \
                 : "=r"(R0), "=r"(R1), "=r"(R2), "=r"(R3) : "r"(A))

__device__ __forceinline__ void mma_bf16(float d[4], const uint32_t a[4], const uint32_t b[2]) {
    asm volatile(
        "mma.sync.aligned.m16n8k16.row.col.f32.bf16.bf16.f32 "
        "{%0,%1,%2,%3}, {%4,%5,%6,%7}, {%8,%9}, {%0,%1,%2,%3};"
        : "+f"(d[0]), "+f"(d[1]), "+f"(d[2]), "+f"(d[3])
        : "r"(a[0]), "r"(a[1]), "r"(a[2]), "r"(a[3]), "r"(b[0]), "r"(b[1]));
}

__device__ __forceinline__ void cpa16(uint32_t saddr, const void* g) {
    asm volatile("cp.async.cg.shared.global [%0], [%1], 16;" :: "r"(saddr), "l"(g));
}
#define CP_COMMIT() asm volatile("cp.async.commit_group;" ::: "memory")
#define CP_WAIT0()  asm volatile("cp.async.wait_group 0;" ::: "memory")

// h = relu( sigmoid(-uz) * tanh(uh) )   [GRU cell with h0 = 0]
__device__ __forceinline__ float gate_act(float uz, float uh) {
    float s = 1.0f / (1.0f + __expf(uz));
    float t = tanhf(uh);
    return fmaxf(s * t, 0.0f);
}

// ---------------- prep: combine W[0,0]+W[1,0], interleave z/h cols, split bf16, swizzle ----------------
__global__ void prep_kernel(const float* __restrict__ wz1, const float* __restrict__ wh1,
                            const float* __restrict__ wz2, const float* __restrict__ wh2) {
    int i = blockIdx.x * blockDim.x + threadIdx.x;   // 65536 threads
    {   // W1: B operand [n=256][k=256]; n=2j -> z_j, n=2j+1 -> h_j
        int nn = i >> 8, k = i & 255;
        int j = nn >> 1;
        const float* src = (nn & 1) ? wh1 : wz1;
        float w = src[k * 128 + j] + src[49152 + k * 128 + j];
        __nv_bfloat16 hb = __float2bfloat16(w);
        __nv_bfloat16 lb = __float2bfloat16(w - __bfloat162float(hb));
        int kt = k >> 6, kk = k & 63;
        uint32_t o = (uint32_t)(kt * 65536) + SW128((uint32_t)(nn * 128 + kk * 2));
        *(__nv_bfloat16*)(g_W1sw + o) = hb;
        *(__nv_bfloat16*)(g_W1sw + o + 32768) = lb;
    }
    if (i < 16384) {   // W2: [n=128][k=128]
        int nn = i >> 7, k = i & 127;
        int j = nn >> 1;
        const float* src = (nn & 1) ? wh2 : wz2;
        float w = src[k * 64 + j] + src[12288 + k * 64 + j];
        __nv_bfloat16 hb = __float2bfloat16(w);
        __nv_bfloat16 lb = __float2bfloat16(w - __bfloat162float(hb));
        int kt = k >> 6, kk = k & 63;
        uint32_t o = (uint32_t)(kt * 32768) + SW128((uint32_t)(nn * 128 + kk * 2));
        *(__nv_bfloat16*)(g_W2sw + o) = hb;
        *(__nv_bfloat16*)(g_W2sw + o + 16384) = lb;
    }
}

// =================== layer 1: BM=128, BN=128 (grid.y = N-half), K=256 ===================
// 256 threads, 2 CTAs/SM.  SMEM (96KB):
//   [0     ] A: hi 16K | lo 16K   (single buffer, 2 syncs/chunk)
//   [32768 ] Bbuf0: hi 16K | lo 16K
//   [65536 ] Bbuf1: hi 16K | lo 16K
// Stage (h1 half-image, 32KB) reuses Bbuf0 after the mainloop.
#define SM1_BYTES 98304

__global__ void __launch_bounds__(256, 2)
layer1_mma(const float* __restrict__ x, const float* __restrict__ bz,
           const float* __restrict__ bh, int n) {
    extern __shared__ __align__(128) char sm[];
    const uint32_t sb = s2u(sm);
    const int tid = threadIdx.x, l = tid & 31, w = tid >> 5;
    const int wm = w >> 1, wn = w & 1;          // 4x2 warp grid, warp tile 32x64
    const int by = blockIdx.y;                  // N-half

    // lane geometry for ldmatrix
    const int arow0 = wm * 32 + (l & 15);
    const uint32_t kba = (uint32_t)(((l >> 4) & 1) * 16);
    const int brow0 = wn * 64 + 8 * ((l >> 4) & 1) + (l & 7);
    const uint32_t kbb = (uint32_t)(((l >> 3) & 1) * 16);

    const int r0 = blockIdx.x * 128;
    const int iq = tid & 15;                    // 16 lanes cover one row's 64 K-values

    float acc[2][8][4];
#pragma unroll
    for (int mi = 0; mi < 2; mi++)
#pragma unroll
        for (int nj = 0; nj < 8; nj++)
#pragma unroll
            for (int q = 0; q < 4; q++) acc[mi][nj][q] = 0.0f;

    float4 xr[8];
    // ---- prologue: x chunk0 into regs, B chunk0 via cp.async ----
#pragma unroll
    for (int p = 0; p < 8; p++) {
        int gr = r0 + (tid >> 4) + p * 16; if (gr >= n) gr = n - 1;
        xr[p] = *(const float4*)(x + (size_t)gr * 256 + iq * 4);
    }
    {
        const char* sh = (const char*)g_W1sw + (size_t)by * 16384;
        const char* sl = sh + 32768;
#pragma unroll
        for (int i = 0; i < 4; i++) {
            int idx = tid + i * 256;
            cpa16(sb + 32768u + (uint32_t)idx * 16u, sh + (size_t)idx * 16);
            cpa16(sb + 49152u + (uint32_t)idx * 16u, sl + (size_t)idx * 16);
        }
        CP_COMMIT();
    }

    // =================== mainloop: 4 K-chunks ===================
    for (int kt = 0; kt < 4; kt++) {
        const uint32_t bB = 32768u + (uint32_t)(kt & 1) * 32768u;

        // store A (A free: end-of-compute sync from prev iter)
#pragma unroll
        for (int p = 0; p < 8; p++) {
            int row = (tid >> 4) + p * 16;
            float4 v = xr[p];
            __nv_bfloat16 h0 = __float2bfloat16(v.x), h1 = __float2bfloat16(v.y);
            __nv_bfloat16 h2 = __float2bfloat16(v.z), h3 = __float2bfloat16(v.w);
            __nv_bfloat16 l0 = __float2bfloat16(v.x - __bfloat162float(h0));
            __nv_bfloat16 l1 = __float2bfloat16(v.y - __bfloat162float(h1));
            __nv_bfloat16 l2 = __float2bfloat16(v.z - __bfloat162float(h2));
            __nv_bfloat16 l3 = __float2bfloat16(v.w - __bfloat162float(h3));
            uint32_t o = SW128((uint32_t)(row * 128 + iq * 8));
            uint2 hp = make_uint2((uint32_t)__bfloat16_as_ushort(h0) | ((uint32_t)__bfloat16_as_ushort(h1) << 16),
                                  (uint32_t)__bfloat16_as_ushort(h2) | ((uint32_t)__bfloat16_as_ushort(h3) << 16));
            uint2 lp = make_uint2((uint32_t)__bfloat16_as_ushort(l0) | ((uint32_t)__bfloat16_as_ushort(l1) << 16),
                                  (uint32_t)__bfloat16_as_ushort(l2) | ((uint32_t)__bfloat16_as_ushort(l3) << 16));
            *(uint2*)(sm + o) = hp;
            *(uint2*)(sm + 16384 + o) = lp;
        }
        // prefetch next x chunk (hidden behind this chunk's compute)
        if (kt < 3) {
#pragma unroll
            for (int p = 0; p < 8; p++) {
                int gr = r0 + (tid >> 4) + p * 16; if (gr >= n) gr = n - 1;
                xr[p] = *(const float4*)(x + (size_t)gr * 256 + (kt + 1) * 64 + iq * 4);
            }
        }
        CP_WAIT0();            // B chunk kt arrived
        __syncthreads();       // A stores + B visible

        // issue next B chunk into the other buffer (overlaps compute)
        if (kt < 3) {
            const char* sh = (const char*)g_W1sw + (size_t)(kt + 1) * 65536 + (size_t)by * 16384;
            const char* sl = sh + 32768;
            uint32_t dstB = 32768u + (uint32_t)((kt + 1) & 1) * 32768u;
#pragma unroll
            for (int i = 0; i < 4; i++) {
                int idx = tid + i * 256;
                cpa16(sb + dstB + (uint32_t)idx * 16u, sh + (size_t)idx * 16);
                cpa16(sb + dstB + 16384u + (uint32_t)idx * 16u, sl + (size_t)idx * 16);
            }
            CP_COMMIT();
        }

        // ---- compute: 3-term split (Ah·Bh, Al·Bh, Ah·Bl) ----
#pragma unroll
        for (int kk = 0; kk < 4; kk++) {
            uint32_t ah[2][4], al[2][4], bfr[8][2];
#pragma unroll
            for (int mi = 0; mi < 2; mi++) {
                int row = arow0 + mi * 16;
                uint32_t off = (uint32_t)(row * 128) + (((uint32_t)(kk * 32) + kba) ^ (uint32_t)((row & 7) << 4));
                LDSM4(ah[mi][0], ah[mi][1], ah[mi][2], ah[mi][3], sb + off);
            }
#pragma unroll
            for (int g = 0; g < 4; g++) {
                int row = brow0 + g * 16;
                uint32_t off = (uint32_t)(row * 128) + (((uint32_t)(kk * 32) + kbb) ^ (uint32_t)((row & 7) << 4));
                LDSM4(bfr[2 * g][0], bfr[2 * g][1], bfr[2 * g + 1][0], bfr[2 * g + 1][1], sb + bB + off);
            }
#pragma unroll
            for (int mi = 0; mi < 2; mi++)
#pragma unroll
                for (int nj = 0; nj < 8; nj++) mma_bf16(acc[mi][nj], ah[mi], bfr[nj]);
#pragma unroll
            for (int mi = 0; mi < 2; mi++) {
                int row = arow0 + mi * 16;
                uint32_t off = (uint32_t)(row * 128) + (((uint32_t)(kk * 32) + kba) ^ (uint32_t)((row & 7) << 4));
                LDSM4(al[mi][0], al[mi][1], al[mi][2], al[mi][3], sb + 16384u + off);
            }
#pragma unroll
            for (int mi = 0; mi < 2; mi++)
#pragma unroll
                for (int nj = 0; nj < 8; nj++) mma_bf16(acc[mi][nj], al[mi], bfr[nj]);
#pragma unroll
            for (int g = 0; g < 4; g++) {
                int row = brow0 + g * 16;
                uint32_t off = (uint32_t)(row * 128) + (((uint32_t)(kk * 32) + kbb) ^ (uint32_t)((row & 7) << 4));
                LDSM4(bfr[2 * g][0], bfr[2 * g][1], bfr[2 * g + 1][0], bfr[2 * g + 1][1], sb + bB + 16384u + off);
            }
#pragma unroll
            for (int mi = 0; mi < 2; mi++)
#pragma unroll
                for (int nj = 0; nj < 8; nj++) mma_bf16(acc[mi][nj], ah[mi], bfr[nj]);
        }
        __syncthreads();       // compute done -> A reusable next iter / stage reusable
    }

    // ---- epilogue: act, bf16 split, stage h1 half-image (ck = by) in Bbuf0 ----
#pragma unroll
    for (int mi = 0; mi < 2; mi++)
#pragma unroll
        for (int nj = 0; nj < 8; nj++) {
            int rlo = wm * 32 + mi * 16 + (l >> 2);
            int j = by * 64 + wn * 32 + nj * 4 + (l & 3);       // global h1 column
            float v0 = gate_act(acc[mi][nj][0] + __ldg(bz + j), acc[mi][nj][1] + __ldg(bh + j));
            float v1 = gate_act(acc[mi][nj][2] + __ldg(bz + j), acc[mi][nj][3] + __ldg(bh + j));
            int kk2 = j & 63;
            {
                __nv_bfloat16 hb = __float2bfloat16(v0);
                __nv_bfloat16 lb = __float2bfloat16(v0 - __bfloat162float(hb));
                uint32_t o = 32768u + SW128((uint32_t)(rlo * 128 + kk2 * 2));
                *(__nv_bfloat16*)(sm + o) = hb;
                *(__nv_bfloat16*)(sm + o + 16384) = lb;
            }
            {
                __nv_bfloat16 hb = __float2bfloat16(v1);
                __nv_bfloat16 lb = __float2bfloat16(v1 - __bfloat162float(hb));
                uint32_t o = 32768u + SW128((uint32_t)((rlo + 8) * 128 + kk2 * 2));
                *(__nv_bfloat16*)(sm + o) = hb;
                *(__nv_bfloat16*)(sm + o + 16384) = lb;
            }
        }
    __syncthreads();
    {   // stage (32KB) -> g_h1img tile section ck=by, coalesced
        const uint4* s4 = (const uint4*)(sm + 32768);
        uint4* d4 = (uint4*)(g_h1img + (size_t)blockIdx.x * 65536 + (size_t)by * 32768);
#pragma unroll
        for (int i = 0; i < 8; i++) d4[tid + i * 256] = s4[tid + i * 256];
    }
}

// =================== layer 2 + lin1 + lin2: BM=128, BN=128, K=128 (2 chunks) ===================
// smem: [A_hi 16K][A_lo 16K][B_hi 16K][B_lo 16K][w3s 4K][b3s][w4s][bzs][bhs]  total 70272
// h2s (128*65*4 = 33280B) overlaps A/B regions after the mainloop.
__global__ void __launch_bounds__(256, 1)
layer2_mma(const float* __restrict__ bz, const float* __restrict__ bh,
           const float* __restrict__ w3, const float* __restrict__ b3,
           const float* __restrict__ w4, const float* __restrict__ b4,
           float* __restrict__ out, int n) {
    extern __shared__ __align__(128) char sm[];
    const uint32_t sb = s2u(sm);
    const int tid = threadIdx.x, l = tid & 31, w = tid >> 5;
    const int wm = w >> 1, wn = w & 1;          // 4x2 warp grid
    float* w3s = (float*)(sm + 65536);
    float* b3s = (float*)(sm + 69632);
    float* w4s = (float*)(sm + 69696);
    float* bzs = (float*)(sm + 69760);
    float* bhs = (float*)(sm + 70016);
#pragma unroll
    for (int i = 0; i < 4; i++) w3s[tid + i * 256] = w3[tid + i * 256];
    if (tid < 16) { b3s[tid] = b3[tid]; w4s[tid] = w4[tid]; }
    if (tid < 64) { bzs[tid] = bz[tid]; bhs[tid] = bh[tid]; }

    float acc[2][8][4];
#pragma unroll
    for (int mi = 0; mi < 2; mi++)
#pragma unroll
        for (int nj = 0; nj < 8; nj++)
#pragma unroll
            for (int q = 0; q < 4; q++) acc[mi][nj][q] = 0.0f;

    const int arow0 = wm * 32 + (l & 15);
    const uint32_t kba = (uint32_t)(((l >> 4) & 1) * 16);
    const int brow0 = wn * 64 + 8 * ((l >> 4) & 1) + (l & 7);
    const uint32_t kbb = (uint32_t)(((l >> 3) & 1) * 16);

    const int r0 = blockIdx.x * 128;

    for (int kt = 0; kt < 2; kt++) {
        {   // A chunk (32KB) + B chunk (32KB) via cp.async
            const char* gA = (const char*)g_h1img + (size_t)blockIdx.x * 65536 + (size_t)kt * 32768;
            const char* gB = (const char*)g_W2sw + (size_t)kt * 32768;
#pragma unroll
            for (int i = 0; i < 8; i++) {
                int idx = tid + i * 256;
                cpa16(sb + (uint32_t)idx * 16u, gA + (size_t)idx * 16);
                cpa16(sb + 32768u + (uint32_t)idx * 16u, gB + (size_t)idx * 16);
            }
            CP_COMMIT();
        }
        CP_WAIT0();
        __syncthreads();

#pragma unroll
        for (int kk = 0; kk < 4; kk++) {
            uint32_t ah[2][4], al[2][4], bfr[8][2];
#pragma unroll
            for (int mi = 0; mi < 2; mi++) {
                int row = arow0 + mi * 16;
                uint32_t off = (uint32_t)(row * 128) + (((uint32_t)(kk * 32) + kba) ^ (uint32_t)((row & 7) << 4));
                LDSM4(ah[mi][0], ah[mi][1], ah[mi][2], ah[mi][3], sb + off);
            }
#pragma unroll
            for (int g = 0; g < 4; g++) {
                int row = brow0 + g * 16;
                uint32_t off = (uint32_t)(row * 128) + (((uint32_t)(kk * 32) + kbb) ^ (uint32_t)((row & 7) << 4));
                LDSM4(bfr[2 * g][0], bfr[2 * g][1], bfr[2 * g + 1][0], bfr[2 * g + 1][1], sb + 32768u + off);
            }
#pragma unroll
            for (int mi = 0; mi < 2; mi++)
#pragma unroll
                for (int nj = 0; nj < 8; nj++) mma_bf16(acc[mi][nj], ah[mi], bfr[nj]);
#pragma unroll
            for (int mi = 0; mi < 2; mi++) {
                int row = arow0 + mi * 16;
                uint32_t off = (uint32_t)(row * 128) + (((uint32_t)(kk * 32) + kba) ^ (uint32_t)((row & 7) << 4));
                LDSM4(al[mi][0], al[mi][1], al[mi][2], al[mi][3], sb + 16384u + off);
            }
#pragma unroll
            for (int mi = 0; mi < 2; mi++)
#pragma unroll
                for (int nj = 0; nj < 8; nj++) mma_bf16(acc[mi][nj], al[mi], bfr[nj]);
#pragma unroll
            for (int g = 0; g < 4; g++) {
                int row = brow0 + g * 16;
                uint32_t off = (uint32_t)(row * 128) + (((uint32_t)(kk * 32) + kbb) ^ (uint32_t)((row & 7) << 4));
                LDSM4(bfr[2 * g][0], bfr[2 * g][1], bfr[2 * g + 1][0], bfr[2 * g + 1][1], sb + 49152u + off);
            }
#pragma unroll
            for (int mi = 0; mi < 2; mi++)
#pragma unroll
                for (int nj = 0; nj < 8; nj++) mma_bf16(acc[mi][nj], ah[mi], bfr[nj]);
        }
        __syncthreads();
    }

    // --- epilogue: h2 -> smem (overlapping dead A/B regions) ---
    float* h2s = (float*)sm;    // [128][65]
#pragma unroll
    for (int mi = 0; mi < 2; mi++)
#pragma unroll
        for (int nj = 0; nj < 8; nj++) {
            int rlo = wm * 32 + mi * 16 + (l >> 2);
            int j = wn * 32 + nj * 4 + (l & 3);
            float v0 = gate_act(acc[mi][nj][0] + bzs[j], acc[mi][nj][1] + bhs[j]);
            float v1 = gate_act(acc[mi][nj][2] + bzs[j], acc[mi][nj][3] + bhs[j]);
            h2s[rlo * 65 + j] = v0;
            h2s[(rlo + 8) * 65 + j] = v1;
        }
    __syncthreads();

    // --- lin1(relu) + lin2: one thread per row ---
    if (tid < 128) {
        float s[16];
#pragma unroll
        for (int u = 0; u < 16; u++) s[u] = b3s[u];
#pragma unroll 4
        for (int j = 0; j < 64; j++) {
            float v = h2s[tid * 65 + j];
#pragma unroll
            for (int u = 0; u < 16; u++) s[u] = fmaf(v, w3s[j * 16 + u], s[u]);
        }
        float o2 = __ldg(b4);
#pragma unroll
        for (int u = 0; u < 16; u++) o2 += fmaxf(s[u], 0.0f) * w4s[u];
        int gr = r0 + tid;
        if (gr < n) out[gr] = o2;
    }
}

extern "C" void kernel_launch(void* const* d_in, const int* in_sizes, int n_in,
                              void* d_out, int out_size) {
    const float* x   = (const float*)d_in[0];
    const float* wz1 = (const float*)d_in[3];
    const float* bz1 = (const float*)d_in[4];
    const float* wh1 = (const float*)d_in[7];
    const float* bh1 = (const float*)d_in[8];
    const float* wz2 = (const float*)d_in[9];
    const float* bz2 = (const float*)d_in[10];
    const float* wh2 = (const float*)d_in[13];
    const float* bh2 = (const float*)d_in[14];
    const float* w3  = (const float*)d_in[15];
    const float* b3  = (const float*)d_in[16];
    const float* w4  = (const float*)d_in[17];
    const float* b4  = (const float*)d_in[18];

    const int n  = in_sizes[0] / 256;          // 100000
    const int nb = (n + 127) / 128;            // 782

    cudaFuncSetAttribute(layer1_mma, cudaFuncAttributeMaxDynamicSharedMemorySize, SM1_BYTES);
    cudaFuncSetAttribute(layer2_mma, cudaFuncAttributeMaxDynamicSharedMemorySize, 70272);

    prep_kernel<<<256, 256>>>(wz1, wh1, wz2, wh2);
    layer1_mma<<<dim3(nb, 2), 256, SM1_BYTES>>>(x, bz1, bh1, n);
    layer2_mma<<<nb, 256, 70272>>>(bz2, bh2, w3, b3, w4, b4, (float*)d_out, n);
}

// round 11
// speedup vs baseline: 1.9229x; 1.4435x over previous
#include <cuda_runtime.h>
#include <cuda_fp16.h>
#include <cstdint>

#define NB_MAX 782            // ceil(100000/128)

// ---------------- device scratch (no allocs allowed) ----------------
// W1 pre-swizzled fp16 images: [kt=4][hi 32KB | lo 32KB]  (B operand [N=256][K=64] per chunk)
__device__ __align__(16) unsigned char g_W1sw[4 * 65536];
// W2 pre-swizzled fp16: [kt=2][hi 16KB | lo 16KB]  ([N=128][K=64] per chunk)
__device__ __align__(16) unsigned char g_W2sw[2 * 32768];
// h1 per-tile A images (single fp16): [ck=2][16KB] = 32KB per 128-row tile
__device__ __align__(16) unsigned char g_h1img[(size_t)NB_MAX * 32768];

// ---------------- helpers ----------------
__device__ __forceinline__ uint32_t s2u(const void* p) {
    uint32_t a;
    asm("{ .reg .u64 t; cvta.to.shared.u64 t, %1; cvt.u32.u64 %0, t; }" : "=r"(a) : "l"(p));
    return a;
}
#define SW128(o) ((o) ^ (((o) >> 3) & 0x70))

#define LDSM4(R0, R1, R2, R3, A) \
    asm volatile("ldmatrix.sync.aligned.m8n8.x4.shared.b16 {%0,%1,%2,%3}, [%4];" \
                 : "=r"(R0), "=r"(R1), "=r"(R2), "=r"(R3) : "r"(A))

__device__ __forceinline__ void mma_f16(float d[4], const uint32_t a[4], const uint32_t b[2]) {
    asm volatile(
        "mma.sync.aligned.m16n8k16.row.col.f32.f16.f16.f32 "
        "{%0,%1,%2,%3}, {%4,%5,%6,%7}, {%8,%9}, {%0,%1,%2,%3};"
        : "+f"(d[0]), "+f"(d[1]), "+f"(d[2]), "+f"(d[3])
        : "r"(a[0]), "r"(a[1]), "r"(a[2]), "r"(a[3]), "r"(b[0]), "r"(b[1]));
}

__device__ __forceinline__ void cpa16(uint32_t saddr, const void* g) {
    asm volatile("cp.async.cg.shared.global [%0], [%1], 16;" :: "r"(saddr), "l"(g));
}
#define CP_COMMIT() asm volatile("cp.async.commit_group;" ::: "memory")
#define CP_WAIT0()  asm volatile("cp.async.wait_group 0;" ::: "memory")

__device__ __forceinline__ uint2 cvt4h(float4 v) {
    __half2 p0 = __floats2half2_rn(v.x, v.y);
    __half2 p1 = __floats2half2_rn(v.z, v.w);
    uint2 r;
    r.x = *reinterpret_cast<uint32_t*>(&p0);
    r.y = *reinterpret_cast<uint32_t*>(&p1);
    return r;
}

// h = relu( sigmoid(-uz) * tanh(uh) )   [GRU cell with h0 = 0]
__device__ __forceinline__ float gate_act(float uz, float uh) {
    float s = 1.0f / (1.0f + __expf(uz));
    float t = tanhf(uh);
    return fmaxf(s * t, 0.0f);
}

// ---------------- prep: combine W[0,0]+W[1,0], interleave z/h cols, split fp16 hi/lo, swizzle ----------------
__global__ void prep_kernel(const float* __restrict__ wz1, const float* __restrict__ wh1,
                            const float* __restrict__ wz2, const float* __restrict__ wh2) {
    int i = blockIdx.x * blockDim.x + threadIdx.x;   // 65536 threads
    {   // W1: B operand [n=256][k=256]; n=2j -> z_j, n=2j+1 -> h_j
        int nn = i >> 8, k = i & 255;
        int j = nn >> 1;
        const float* src = (nn & 1) ? wh1 : wz1;
        float w = src[k * 128 + j] + src[49152 + k * 128 + j];
        __half hb = __float2half_rn(w);
        __half lb = __float2half_rn(w - __half2float(hb));
        int kt = k >> 6, kk = k & 63;
        uint32_t o = (uint32_t)(kt * 65536) + SW128((uint32_t)(nn * 128 + kk * 2));
        *(__half*)(g_W1sw + o) = hb;
        *(__half*)(g_W1sw + o + 32768) = lb;
    }
    if (i < 16384) {   // W2: [n=128][k=128]
        int nn = i >> 7, k = i & 127;
        int j = nn >> 1;
        const float* src = (nn & 1) ? wh2 : wz2;
        float w = src[k * 64 + j] + src[12288 + k * 64 + j];
        __half hb = __float2half_rn(w);
        __half lb = __float2half_rn(w - __half2float(hb));
        int kt = k >> 6, kk = k & 63;
        uint32_t o = (uint32_t)(kt * 32768) + SW128((uint32_t)(nn * 128 + kk * 2));
        *(__half*)(g_W2sw + o) = hb;
        *(__half*)(g_W2sw + o + 16384) = lb;
    }
}

// =================== layer 1: BM=128, BN=128 (grid.y = N-half), K=256, fp16 2-term ===================
// 256 threads, 2 CTAs/SM.  SMEM (96KB):
//   [0     ] A0 16K   [16384] A1 16K       (x chunk, single fp16)
//   [32768 ] B0 32K (hi 16K | lo 16K)  [65536] B1 32K
// Stage (h1 half-image, 16KB) reuses B0 region after the mainloop.
#define SM1_BYTES 98304

__global__ void __launch_bounds__(256, 2)
layer1_mma(const float* __restrict__ x, const float* __restrict__ bz,
           const float* __restrict__ bh, int n) {
    extern __shared__ __align__(128) char sm[];
    const uint32_t sb = s2u(sm);
    const int tid = threadIdx.x, l = tid & 31, w = tid >> 5;
    const int wm = w >> 1, wn = w & 1;          // 4x2 warp grid, warp tile 32x64
    const int by = blockIdx.y;                  // N-half

    const int arow0 = wm * 32 + (l & 15);
    const uint32_t kba = (uint32_t)(((l >> 4) & 1) * 16);
    const int brow0 = wn * 64 + 8 * ((l >> 4) & 1) + (l & 7);
    const uint32_t kbb = (uint32_t)(((l >> 3) & 1) * 16);

    const int r0 = blockIdx.x * 128;
    const int iq = tid & 15;                    // 16 lanes cover one row's 64 K-values

    float acc[2][8][4];
#pragma unroll
    for (int mi = 0; mi < 2; mi++)
#pragma unroll
        for (int nj = 0; nj < 8; nj++)
#pragma unroll
            for (int q = 0; q < 4; q++) acc[mi][nj][q] = 0.0f;

    uint2 xh[8];
    // ---- prologue: x chunk0 -> fp16 regs, B chunk0 via cp.async ----
#pragma unroll
    for (int p = 0; p < 8; p++) {
        int gr = r0 + (tid >> 4) + p * 16; if (gr >= n) gr = n - 1;
        xh[p] = cvt4h(*(const float4*)(x + (size_t)gr * 256 + iq * 4));
    }
    {
        const char* sh = (const char*)g_W1sw + (size_t)by * 16384;
        const char* sl = sh + 32768;
#pragma unroll
        for (int i = 0; i < 4; i++) {
            int idx = tid + i * 256;
            cpa16(sb + 32768u + (uint32_t)idx * 16u, sh + (size_t)idx * 16);
            cpa16(sb + 49152u + (uint32_t)idx * 16u, sl + (size_t)idx * 16);
        }
        CP_COMMIT();
    }

    // =================== mainloop: 4 K-chunks, fully double-buffered, 1 sync/chunk ===================
    for (int kt = 0; kt < 4; kt++) {
        const uint32_t aB = (uint32_t)(kt & 1) * 16384u;
        const uint32_t bB = 32768u + (uint32_t)(kt & 1) * 32768u;

        // store A chunk kt (safe: all warps passed previous sync => done reading this buffer)
#pragma unroll
        for (int p = 0; p < 8; p++) {
            int row = (tid >> 4) + p * 16;
            uint32_t o = aB + SW128((uint32_t)(row * 128 + iq * 8));
            *(uint2*)(sm + o) = xh[p];
        }
        // prefetch + convert next x chunk (hidden behind this chunk's compute)
        if (kt < 3) {
#pragma unroll
            for (int p = 0; p < 8; p++) {
                int gr = r0 + (tid >> 4) + p * 16; if (gr >= n) gr = n - 1;
                xh[p] = cvt4h(*(const float4*)(x + (size_t)gr * 256 + (kt + 1) * 64 + iq * 4));
            }
        }
        CP_WAIT0();            // B chunk kt arrived
        __syncthreads();       // A stores + B visible; prior chunk's readers done

        // issue next B chunk into the other buffer (lands during this chunk's compute)
        if (kt < 3) {
            const char* sh = (const char*)g_W1sw + (size_t)(kt + 1) * 65536 + (size_t)by * 16384;
            const char* sl = sh + 32768;
            uint32_t dstB = 32768u + (uint32_t)((kt + 1) & 1) * 32768u;
#pragma unroll
            for (int i = 0; i < 4; i++) {
                int idx = tid + i * 256;
                cpa16(sb + dstB + (uint32_t)idx * 16u, sh + (size_t)idx * 16);
                cpa16(sb + dstB + 16384u + (uint32_t)idx * 16u, sl + (size_t)idx * 16);
            }
            CP_COMMIT();
        }

        // ---- compute: 2-term (A·Bh, A·Bl) ----
#pragma unroll
        for (int kk = 0; kk < 4; kk++) {
            uint32_t af[2][4], bfr[8][2];
#pragma unroll
            for (int mi = 0; mi < 2; mi++) {
                int row = arow0 + mi * 16;
                uint32_t off = (uint32_t)(row * 128) + (((uint32_t)(kk * 32) + kba) ^ (uint32_t)((row & 7) << 4));
                LDSM4(af[mi][0], af[mi][1], af[mi][2], af[mi][3], sb + aB + off);
            }
#pragma unroll
            for (int g = 0; g < 4; g++) {
                int row = brow0 + g * 16;
                uint32_t off = (uint32_t)(row * 128) + (((uint32_t)(kk * 32) + kbb) ^ (uint32_t)((row & 7) << 4));
                LDSM4(bfr[2 * g][0], bfr[2 * g][1], bfr[2 * g + 1][0], bfr[2 * g + 1][1], sb + bB + off);
            }
#pragma unroll
            for (int mi = 0; mi < 2; mi++)
#pragma unroll
                for (int nj = 0; nj < 8; nj++) mma_f16(acc[mi][nj], af[mi], bfr[nj]);
#pragma unroll
            for (int g = 0; g < 4; g++) {
                int row = brow0 + g * 16;
                uint32_t off = (uint32_t)(row * 128) + (((uint32_t)(kk * 32) + kbb) ^ (uint32_t)((row & 7) << 4));
                LDSM4(bfr[2 * g][0], bfr[2 * g][1], bfr[2 * g + 1][0], bfr[2 * g + 1][1], sb + bB + 16384u + off);
            }
#pragma unroll
            for (int mi = 0; mi < 2; mi++)
#pragma unroll
                for (int nj = 0; nj < 8; nj++) mma_f16(acc[mi][nj], af[mi], bfr[nj]);
        }
    }

    // ---- epilogue: act, single fp16, stage h1 half-image (ck = by) in B0 region ----
    // Stage [32768, 49152) is disjoint from kt=3's live buffers (A1, B1) => no sync needed first.
#pragma unroll
    for (int mi = 0; mi < 2; mi++)
#pragma unroll
        for (int nj = 0; nj < 8; nj++) {
            int rlo = wm * 32 + mi * 16 + (l >> 2);
            int j = by * 64 + wn * 32 + nj * 4 + (l & 3);       // global h1 column
            float v0 = gate_act(acc[mi][nj][0] + __ldg(bz + j), acc[mi][nj][1] + __ldg(bh + j));
            float v1 = gate_act(acc[mi][nj][2] + __ldg(bz + j), acc[mi][nj][3] + __ldg(bh + j));
            int kk2 = j & 63;
            uint32_t o0 = 32768u + SW128((uint32_t)(rlo * 128 + kk2 * 2));
            uint32_t o1 = 32768u + SW128((uint32_t)((rlo + 8) * 128 + kk2 * 2));
            *(__half*)(sm + o0) = __float2half_rn(v0);
            *(__half*)(sm + o1) = __float2half_rn(v1);
        }
    __syncthreads();
    {   // stage (16KB) -> g_h1img tile section ck=by, coalesced
        const uint4* s4 = (const uint4*)(sm + 32768);
        uint4* d4 = (uint4*)(g_h1img + (size_t)blockIdx.x * 32768 + (size_t)by * 16384);
#pragma unroll
        for (int i = 0; i < 4; i++) d4[tid + i * 256] = s4[tid + i * 256];
    }
}

// =================== layer 2 + lin1 + lin2: BM=128, BN=128, K=128 (2 chunks), fp16 2-term ===================
// SMEM: [0] A0 16K [16384] A1 16K [32768] B0 32K [65536] B1 32K
//       [98304] w3s 4K [102400] b3s 64B [102464] w4s 64B [102528] bzs 256B [102784] bhs 256B
// h2s (128*65*4 = 33280B) overlaps [0, 33280) after the mainloop.
#define SM2_BYTES 103040

__global__ void __launch_bounds__(256, 2)
layer2_mma(const float* __restrict__ bz, const float* __restrict__ bh,
           const float* __restrict__ w3, const float* __restrict__ b3,
           const float* __restrict__ w4, const float* __restrict__ b4,
           float* __restrict__ out, int n) {
    extern __shared__ __align__(128) char sm[];
    const uint32_t sb = s2u(sm);
    const int tid = threadIdx.x, l = tid & 31, w = tid >> 5;
    const int wm = w >> 1, wn = w & 1;          // 4x2 warp grid, warp tile 32x64
    float* w3s = (float*)(sm + 98304);
    float* b3s = (float*)(sm + 102400);
    float* w4s = (float*)(sm + 102464);
    float* bzs = (float*)(sm + 102528);
    float* bhs = (float*)(sm + 102784);
#pragma unroll
    for (int i = 0; i < 4; i++) w3s[tid + i * 256] = w3[tid + i * 256];
    if (tid < 16) { b3s[tid] = b3[tid]; w4s[tid] = w4[tid]; }
    if (tid < 64) { bzs[tid] = bz[tid]; bhs[tid] = bh[tid]; }

    float acc[2][8][4];
#pragma unroll
    for (int mi = 0; mi < 2; mi++)
#pragma unroll
        for (int nj = 0; nj < 8; nj++)
#pragma unroll
            for (int q = 0; q < 4; q++) acc[mi][nj][q] = 0.0f;

    const int arow0 = wm * 32 + (l & 15);
    const uint32_t kba = (uint32_t)(((l >> 4) & 1) * 16);
    const int brow0 = wn * 64 + 8 * ((l >> 4) & 1) + (l & 7);
    const uint32_t kbb = (uint32_t)(((l >> 3) & 1) * 16);

    const int r0 = blockIdx.x * 128;

    // ---- prologue: A0 (16K) + B0 (32K) via cp.async ----
    {
        const char* gA = (const char*)g_h1img + (size_t)blockIdx.x * 32768;
        const char* gB = (const char*)g_W2sw;
#pragma unroll
        for (int i = 0; i < 4; i++) {
            int idx = tid + i * 256;
            cpa16(sb + (uint32_t)idx * 16u, gA + (size_t)idx * 16);
        }
#pragma unroll
        for (int i = 0; i < 8; i++) {
            int idx = tid + i * 256;
            cpa16(sb + 32768u + (uint32_t)idx * 16u, gB + (size_t)idx * 16);
        }
        CP_COMMIT();
    }

    for (int kt = 0; kt < 2; kt++) {
        const uint32_t aB = (uint32_t)kt * 16384u;
        const uint32_t bB = 32768u + (uint32_t)kt * 32768u;

        CP_WAIT0();
        __syncthreads();

        if (kt == 0) {   // prefetch chunk 1 during chunk 0 compute
            const char* gA = (const char*)g_h1img + (size_t)blockIdx.x * 32768 + 16384;
            const char* gB = (const char*)g_W2sw + 32768;
#pragma unroll
            for (int i = 0; i < 4; i++) {
                int idx = tid + i * 256;
                cpa16(sb + 16384u + (uint32_t)idx * 16u, gA + (size_t)idx * 16);
            }
#pragma unroll
            for (int i = 0; i < 8; i++) {
                int idx = tid + i * 256;
                cpa16(sb + 65536u + (uint32_t)idx * 16u, gB + (size_t)idx * 16);
            }
            CP_COMMIT();
        }

        // ---- compute: 2-term (A·Bh, A·Bl) ----
#pragma unroll
        for (int kk = 0; kk < 4; kk++) {
            uint32_t af[2][4], bfr[8][2];
#pragma unroll
            for (int mi = 0; mi < 2; mi++) {
                int row = arow0 + mi * 16;
                uint32_t off = (uint32_t)(row * 128) + (((uint32_t)(kk * 32) + kba) ^ (uint32_t)((row & 7) << 4));
                LDSM4(af[mi][0], af[mi][1], af[mi][2], af[mi][3], sb + aB + off);
            }
#pragma unroll
            for (int g = 0; g < 4; g++) {
                int row = brow0 + g * 16;
                uint32_t off = (uint32_t)(row * 128) + (((uint32_t)(kk * 32) + kbb) ^ (uint32_t)((row & 7) << 4));
                LDSM4(bfr[2 * g][0], bfr[2 * g][1], bfr[2 * g + 1][0], bfr[2 * g + 1][1], sb + bB + off);
            }
#pragma unroll
            for (int mi = 0; mi < 2; mi++)
#pragma unroll
                for (int nj = 0; nj < 8; nj++) mma_f16(acc[mi][nj], af[mi], bfr[nj]);
#pragma unroll
            for (int g = 0; g < 4; g++) {
                int row = brow0 + g * 16;
                uint32_t off = (uint32_t)(row * 128) + (((uint32_t)(kk * 32) + kbb) ^ (uint32_t)((row & 7) << 4));
                LDSM4(bfr[2 * g][0], bfr[2 * g][1], bfr[2 * g + 1][0], bfr[2 * g + 1][1], sb + bB + 16384u + off);
            }
#pragma unroll
            for (int mi = 0; mi < 2; mi++)
#pragma unroll
                for (int nj = 0; nj < 8; nj++) mma_f16(acc[mi][nj], af[mi], bfr[nj]);
        }
    }
    __syncthreads();   // all compute done before h2s overwrites A/B regions

    // ---- epilogue: h2 -> smem ----
    float* h2s = (float*)sm;    // [128][65]
#pragma unroll
    for (int mi = 0; mi < 2; mi++)
#pragma unroll
        for (int nj = 0; nj < 8; nj++) {
            int rlo = wm * 32 + mi * 16 + (l >> 2);
            int j = wn * 32 + nj * 4 + (l & 3);
            float v0 = gate_act(acc[mi][nj][0] + bzs[j], acc[mi][nj][1] + bhs[j]);
            float v1 = gate_act(acc[mi][nj][2] + bzs[j], acc[mi][nj][3] + bhs[j]);
            h2s[rlo * 65 + j] = v0;
            h2s[(rlo + 8) * 65 + j] = v1;
        }
    __syncthreads();

    // ---- lin1(relu) + lin2: one thread per row ----
    if (tid < 128) {
        float s[16];
#pragma unroll
        for (int u = 0; u < 16; u++) s[u] = b3s[u];
#pragma unroll 4
        for (int j = 0; j < 64; j++) {
            float v = h2s[tid * 65 + j];
#pragma unroll
            for (int u = 0; u < 16; u++) s[u] = fmaf(v, w3s[j * 16 + u], s[u]);
        }
        float o2 = __ldg(b4);
#pragma unroll
        for (int u = 0; u < 16; u++) o2 += fmaxf(s[u], 0.0f) * w4s[u];
        int gr = r0 + tid;
        if (gr < n) out[gr] = o2;
    }
}

extern "C" void kernel_launch(void* const* d_in, const int* in_sizes, int n_in,
                              void* d_out, int out_size) {
    const float* x   = (const float*)d_in[0];
    const float* wz1 = (const float*)d_in[3];
    const float* bz1 = (const float*)d_in[4];
    const float* wh1 = (const float*)d_in[7];
    const float* bh1 = (const float*)d_in[8];
    const float* wz2 = (const float*)d_in[9];
    const float* bz2 = (const float*)d_in[10];
    const float* wh2 = (const float*)d_in[13];
    const float* bh2 = (const float*)d_in[14];
    const float* w3  = (const float*)d_in[15];
    const float* b3  = (const float*)d_in[16];
    const float* w4  = (const float*)d_in[17];
    const float* b4  = (const float*)d_in[18];

    const int n  = in_sizes[0] / 256;          // 100000
    const int nb = (n + 127) / 128;            // 782

    cudaFuncSetAttribute(layer1_mma, cudaFuncAttributeMaxDynamicSharedMemorySize, SM1_BYTES);
    cudaFuncSetAttribute(layer2_mma, cudaFuncAttributeMaxDynamicSharedMemorySize, SM2_BYTES);

    prep_kernel<<<256, 256>>>(wz1, wh1, wz2, wh2);
    layer1_mma<<<dim3(nb, 2), 256, SM1_BYTES>>>(x, bz1, bh1, n);
    layer2_mma<<<nb, 256, SM2_BYTES>>>(bz2, bh2, w3, b3, w4, b4, (float*)d_out, n);
}